// round 1
// baseline (speedup 1.0000x reference)
#include <cuda_runtime.h>
#include <cuda_bf16.h>
#include <cstddef>

// Problem constants (fixed by the reference)
#define NSRC0 200000
#define NDST0 50000
#define NDST1 10000
#define E0    800000
#define E1    160000
#define D     128

// ---------------- device scratch (static globals; no allocation) ----------------
__device__ float g_h0[(size_t)NSRC0 * D];    // relu(features @ W_init + b_init)
__device__ float g_h1[(size_t)NDST0 * D];    // layer-1 output
__device__ float g_agg0[(size_t)NDST0 * D];  // mean-aggregated neighbors, block 0
__device__ float g_agg1[(size_t)NDST1 * D];  // mean-aggregated neighbors, block 1

__device__ int g_cnt0[NDST0];
__device__ int g_off0[NDST0 + 1];
__device__ int g_cur0[NDST0];
__device__ int g_esrc0[E0];

__device__ int g_cnt1[NDST1];
__device__ int g_off1[NDST1 + 1];
__device__ int g_cur1[NDST1];
__device__ int g_esrc1[E1];

// ---------------- CSR build ----------------

__global__ void zero_counts_kernel() {
    int i = blockIdx.x * blockDim.x + threadIdx.x;
    if (i < NDST0) g_cnt0[i] = 0;
    if (i < NDST1) g_cnt1[i] = 0;
}

__global__ void hist_kernel(const int* __restrict__ dst0, const int* __restrict__ dst1) {
    int i = blockIdx.x * blockDim.x + threadIdx.x;
    if (i < E0) atomicAdd(&g_cnt0[dst0[i]], 1);
    if (i < E1) atomicAdd(&g_cnt1[dst1[i]], 1);
}

// Single-block exclusive scan per graph. blockIdx.x == 0 -> graph0, == 1 -> graph1.
__global__ void scan_kernel() {
    __shared__ int sums[1024];
    const int tid = threadIdx.x;
    const int n       = (blockIdx.x == 0) ? NDST0 : NDST1;
    int*      cnt     = (blockIdx.x == 0) ? g_cnt0 : g_cnt1;
    int*      off     = (blockIdx.x == 0) ? g_off0 : g_off1;
    int*      cur     = (blockIdx.x == 0) ? g_cur0 : g_cur1;

    const int per   = (n + 1023) / 1024;
    const int start = tid * per;
    const int end   = min(start + per, n);

    int s = 0;
    for (int i = start; i < end; i++) s += cnt[i];
    sums[tid] = s;
    __syncthreads();

    // Hillis-Steele inclusive scan over 1024 partials
    for (int d = 1; d < 1024; d <<= 1) {
        int v = (tid >= d) ? sums[tid - d] : 0;
        __syncthreads();
        sums[tid] += v;
        __syncthreads();
    }

    int run = (tid == 0) ? 0 : sums[tid - 1];
    for (int i = start; i < end; i++) {
        off[i] = run;
        cur[i] = run;
        run += cnt[i];
    }
    if (tid == 0) off[n] = sums[1023];
}

__global__ void scatter_kernel(const int* __restrict__ src0, const int* __restrict__ dst0,
                               const int* __restrict__ src1, const int* __restrict__ dst1) {
    int i = blockIdx.x * blockDim.x + threadIdx.x;
    if (i < E0) {
        int pos = atomicAdd(&g_cur0[dst0[i]], 1);
        g_esrc0[pos] = src0[i];
    }
    if (i < E1) {
        int pos = atomicAdd(&g_cur1[dst1[i]], 1);
        g_esrc1[pos] = src1[i];
    }
}

// ---------------- mean aggregation: one warp per destination node ----------------
__global__ void aggregate_kernel(const float* __restrict__ h, const int* __restrict__ off,
                                 const int* __restrict__ esrc, float* __restrict__ agg,
                                 int ndst) {
    int gw   = (blockIdx.x * blockDim.x + threadIdx.x) >> 5;
    int lane = threadIdx.x & 31;
    if (gw >= ndst) return;

    int s = off[gw], e = off[gw + 1];
    float4 acc = make_float4(0.f, 0.f, 0.f, 0.f);
    for (int i = s; i < e; i++) {
        const float4* row = reinterpret_cast<const float4*>(h + (size_t)esrc[i] * D);
        float4 v = __ldg(&row[lane]);
        acc.x += v.x; acc.y += v.y; acc.z += v.z; acc.w += v.w;
    }
    float inv = 1.0f / fmaxf((float)(e - s), 1.0f);
    acc.x *= inv; acc.y *= inv; acc.z *= inv; acc.w *= inv;
    reinterpret_cast<float4*>(agg + (size_t)gw * D)[lane] = acc;
}

// ---------------- tiled fp32 GEMM: C[M,128] = op(A1@B1 (+ A2@B2) + bias), N=K=128 ----------------
// 256 threads, 128x128 tile, each thread an 8x8 microtile, K streamed in chunks of 16.
template <int RELU, int DUAL>
__global__ void __launch_bounds__(256, 2)
gemm128_kernel(const float* __restrict__ A1, const float* __restrict__ B1,
               const float* __restrict__ A2, const float* __restrict__ B2,
               const float* __restrict__ bias1, const float* __restrict__ bias2,
               float* __restrict__ C, int M) {
    __shared__ float As[16][D + 4];
    __shared__ float Bs[16][D + 4];

    const int t  = threadIdx.x;
    const int ty = t >> 4;    // 0..15 (row group)
    const int tx = t & 15;    // 0..15 (col group)
    const int m0 = blockIdx.x * 128;

    float acc[8][8];
    #pragma unroll
    for (int i = 0; i < 8; i++)
        #pragma unroll
        for (int j = 0; j < 8; j++) acc[i][j] = 0.f;

    const int nphase = DUAL ? 2 : 1;
    for (int p = 0; p < nphase; p++) {
        const float* A = (DUAL && p == 1) ? A2 : A1;
        const float* B = (DUAL && p == 1) ? B2 : B1;

        for (int k0 = 0; k0 < D; k0 += 16) {
            // Load A chunk: rows [m0, m0+128), cols [k0, k0+16), transposed to As[k][m]
            #pragma unroll
            for (int j = 0; j < 2; j++) {
                int lin = t + 256 * j;        // 0..511 float4s
                int m   = lin >> 2;           // 0..127
                int kq  = lin & 3;            // 0..3
                int gm  = m0 + m;
                float4 v = make_float4(0.f, 0.f, 0.f, 0.f);
                if (gm < M)
                    v = *reinterpret_cast<const float4*>(A + (size_t)gm * D + k0 + kq * 4);
                As[kq * 4 + 0][m] = v.x;
                As[kq * 4 + 1][m] = v.y;
                As[kq * 4 + 2][m] = v.z;
                As[kq * 4 + 3][m] = v.w;
            }
            // Load B chunk: rows [k0, k0+16), all 128 cols
            #pragma unroll
            for (int j = 0; j < 2; j++) {
                int lin = t + 256 * j;        // 0..511
                int k   = lin >> 5;           // 0..15
                int nq  = lin & 31;           // 0..31
                float4 v = *reinterpret_cast<const float4*>(B + (size_t)(k0 + k) * D + nq * 4);
                *reinterpret_cast<float4*>(&Bs[k][nq * 4]) = v;
            }
            __syncthreads();

            #pragma unroll
            for (int kk = 0; kk < 16; kk++) {
                float a[8], b[8];
                *reinterpret_cast<float4*>(a)     = *reinterpret_cast<float4*>(&As[kk][ty * 8]);
                *reinterpret_cast<float4*>(a + 4) = *reinterpret_cast<float4*>(&As[kk][ty * 8 + 4]);
                *reinterpret_cast<float4*>(b)     = *reinterpret_cast<float4*>(&Bs[kk][tx * 8]);
                *reinterpret_cast<float4*>(b + 4) = *reinterpret_cast<float4*>(&Bs[kk][tx * 8 + 4]);
                #pragma unroll
                for (int i = 0; i < 8; i++)
                    #pragma unroll
                    for (int j = 0; j < 8; j++)
                        acc[i][j] = fmaf(a[i], b[j], acc[i][j]);
            }
            __syncthreads();
        }
    }

    // Epilogue: bias (+bias2 if DUAL), optional relu, vectorized store
    float bsum[8];
    #pragma unroll
    for (int j = 0; j < 8; j++) {
        float bv = bias1[tx * 8 + j];
        if (DUAL) bv += bias2[tx * 8 + j];
        bsum[j] = bv;
    }
    #pragma unroll
    for (int i = 0; i < 8; i++) {
        int gm = m0 + ty * 8 + i;
        if (gm >= M) continue;
        #pragma unroll
        for (int jq = 0; jq < 2; jq++) {
            float4 v;
            v.x = acc[i][jq * 4 + 0] + bsum[jq * 4 + 0];
            v.y = acc[i][jq * 4 + 1] + bsum[jq * 4 + 1];
            v.z = acc[i][jq * 4 + 2] + bsum[jq * 4 + 2];
            v.w = acc[i][jq * 4 + 3] + bsum[jq * 4 + 3];
            if (RELU) {
                v.x = fmaxf(v.x, 0.f); v.y = fmaxf(v.y, 0.f);
                v.z = fmaxf(v.z, 0.f); v.w = fmaxf(v.w, 0.f);
            }
            *reinterpret_cast<float4*>(C + (size_t)gm * D + tx * 8 + jq * 4) = v;
        }
    }
}

// ---------------- launch ----------------
extern "C" void kernel_launch(void* const* d_in, const int* in_sizes, int n_in,
                              void* d_out, int out_size) {
    const float* features = (const float*)d_in[0];
    const int*   src0     = (const int*)d_in[1];
    const int*   dst0     = (const int*)d_in[2];
    const int*   src1     = (const int*)d_in[3];
    const int*   dst1     = (const int*)d_in[4];
    const float* W_init   = (const float*)d_in[5];
    const float* b_init   = (const float*)d_in[6];
    const float* W_self   = (const float*)d_in[7];
    const float* b_self   = (const float*)d_in[8];
    const float* W_neigh  = (const float*)d_in[9];
    const float* b_neigh  = (const float*)d_in[10];
    float*       out      = (float*)d_out;

    // resolve device-global addresses (host-side, graph-capture safe)
    float *h0, *h1, *agg0, *agg1;
    int *off0, *esrc0, *off1, *esrc1;
    cudaGetSymbolAddress((void**)&h0, g_h0);
    cudaGetSymbolAddress((void**)&h1, g_h1);
    cudaGetSymbolAddress((void**)&agg0, g_agg0);
    cudaGetSymbolAddress((void**)&agg1, g_agg1);
    cudaGetSymbolAddress((void**)&off0, g_off0);
    cudaGetSymbolAddress((void**)&esrc0, g_esrc0);
    cudaGetSymbolAddress((void**)&off1, g_off1);
    cudaGetSymbolAddress((void**)&esrc1, g_esrc1);

    // --- CSR build for both graphs (independent of GEMM1) ---
    zero_counts_kernel<<<(NDST0 + 255) / 256, 256>>>();
    hist_kernel<<<(E0 + 255) / 256, 256>>>(dst0, dst1);
    scan_kernel<<<2, 1024>>>();
    scatter_kernel<<<(E0 + 255) / 256, 256>>>(src0, dst0, src1, dst1);

    // --- layer 0: h0 = relu(features @ W_init + b_init), M = 200000 ---
    gemm128_kernel<1, 0><<<(NSRC0 + 127) / 128, 256>>>(
        features, W_init, nullptr, nullptr, b_init, nullptr, h0, NSRC0);

    // --- block 0 mean aggregation -> agg0 [50000,128] ---
    aggregate_kernel<<<(NDST0 * 32 + 255) / 256, 256>>>(h0, off0, esrc0, agg0, NDST0);

    // --- layer 1: h1 = relu(h0[:50000]@W_self + b_self + agg0@W_neigh + b_neigh) ---
    gemm128_kernel<1, 1><<<(NDST0 + 127) / 128, 256>>>(
        h0, W_self, agg0, W_neigh, b_self, b_neigh, h1, NDST0);

    // --- block 1 mean aggregation -> agg1 [10000,128] ---
    aggregate_kernel<<<(NDST1 * 32 + 255) / 256, 256>>>(h1, off1, esrc1, agg1, NDST1);

    // --- layer 2 (no relu): out = h1[:10000]@W_self + b_self + agg1@W_neigh + b_neigh ---
    gemm128_kernel<0, 1><<<(NDST1 + 127) / 128, 256>>>(
        h1, W_self, agg1, W_neigh, b_self, b_neigh, out, NDST1);
}

// round 4
// speedup vs baseline: 1.5693x; 1.5693x over previous
#include <cuda_runtime.h>
#include <cuda_bf16.h>
#include <cstdint>
#include <cstddef>

// Problem constants (fixed by the reference)
#define NSRC0 200000
#define NDST0 50000
#define NDST1 10000
#define E0    800000
#define E1    160000
#define D     128

#define AS 132  // padded smem row stride (floats): bank = (4*row + col) % 32 -> conflict-free frags

// ---------------- device scratch (static globals; no allocation) ----------------
__device__ float g_h0[(size_t)NSRC0 * D];
__device__ float g_h1[(size_t)NDST0 * D];
__device__ float g_agg0[(size_t)NDST0 * D];
__device__ float g_agg1[(size_t)NDST1 * D];

__device__ int g_cnt0[NDST0];
__device__ int g_off0[NDST0 + 1];
__device__ int g_cur0[NDST0];
__device__ int g_esrc0[E0];

__device__ int g_cnt1[NDST1];
__device__ int g_off1[NDST1 + 1];
__device__ int g_cur1[NDST1];
__device__ int g_esrc1[E1];

// ---------------- helpers ----------------
__device__ __forceinline__ uint32_t smem_u32(const void* p) {
    uint32_t a;
    asm("{ .reg .u64 t; cvta.to.shared.u64 t, %1; cvt.u32.u64 %0, t; }" : "=r"(a) : "l"(p));
    return a;
}
__device__ __forceinline__ uint32_t f2tf(float f) {
    uint32_t r;
    asm("cvt.rna.tf32.f32 %0, %1;" : "=r"(r) : "f"(f));
    return r;
}
#define CP_ASYNC16(dst, src) \
    asm volatile("cp.async.cg.shared.global [%0], [%1], 16;" :: "r"(dst), "l"(src) : "memory")
#define CP_COMMIT() asm volatile("cp.async.commit_group;" ::: "memory")
#define CP_WAIT0()  asm volatile("cp.async.wait_group 0;" ::: "memory")

__device__ __forceinline__ void mma_tf32(float d[4], const uint32_t a[4], uint32_t b0, uint32_t b1) {
    asm volatile(
        "mma.sync.aligned.m16n8k8.row.col.f32.tf32.tf32.f32 "
        "{%0,%1,%2,%3}, {%4,%5,%6,%7}, {%8,%9}, {%0,%1,%2,%3};"
        : "+f"(d[0]), "+f"(d[1]), "+f"(d[2]), "+f"(d[3])
        : "r"(a[0]), "r"(a[1]), "r"(a[2]), "r"(a[3]), "r"(b0), "r"(b1));
}

// ---------------- CSR build (from R1, proven) ----------------
__global__ void zero_counts_kernel() {
    int i = blockIdx.x * blockDim.x + threadIdx.x;
    if (i < NDST0) g_cnt0[i] = 0;
    if (i < NDST1) g_cnt1[i] = 0;
}
__global__ void hist_kernel(const int* __restrict__ dst0, const int* __restrict__ dst1) {
    int i = blockIdx.x * blockDim.x + threadIdx.x;
    if (i < E0) atomicAdd(&g_cnt0[dst0[i]], 1);
    if (i < E1) atomicAdd(&g_cnt1[dst1[i]], 1);
}
__global__ void scan_kernel() {
    __shared__ int sums[1024];
    const int tid = threadIdx.x;
    const int n   = (blockIdx.x == 0) ? NDST0 : NDST1;
    int* cnt = (blockIdx.x == 0) ? g_cnt0 : g_cnt1;
    int* off = (blockIdx.x == 0) ? g_off0 : g_off1;
    int* cur = (blockIdx.x == 0) ? g_cur0 : g_cur1;
    const int per = (n + 1023) / 1024;
    const int start = tid * per;
    const int end = min(start + per, n);
    int s = 0;
    for (int i = start; i < end; i++) s += cnt[i];
    sums[tid] = s;
    __syncthreads();
    for (int d = 1; d < 1024; d <<= 1) {
        int v = (tid >= d) ? sums[tid - d] : 0;
        __syncthreads();
        sums[tid] += v;
        __syncthreads();
    }
    int run = (tid == 0) ? 0 : sums[tid - 1];
    for (int i = start; i < end; i++) {
        off[i] = run; cur[i] = run; run += cnt[i];
    }
    if (tid == 0) off[n] = sums[1023];
}
__global__ void scatter_kernel(const int* __restrict__ src0, const int* __restrict__ dst0,
                               const int* __restrict__ src1, const int* __restrict__ dst1) {
    int i = blockIdx.x * blockDim.x + threadIdx.x;
    if (i < E0) { int pos = atomicAdd(&g_cur0[dst0[i]], 1); g_esrc0[pos] = src0[i]; }
    if (i < E1) { int pos = atomicAdd(&g_cur1[dst1[i]], 1); g_esrc1[pos] = src1[i]; }
}

// ---------------- mean aggregation: one warp per destination node ----------------
__global__ void aggregate_kernel(const float* __restrict__ h, const int* __restrict__ off,
                                 const int* __restrict__ esrc, float* __restrict__ agg,
                                 int ndst) {
    int gw = (blockIdx.x * blockDim.x + threadIdx.x) >> 5;
    int lane = threadIdx.x & 31;
    if (gw >= ndst) return;
    int s = off[gw], e = off[gw + 1];
    float4 acc = make_float4(0.f, 0.f, 0.f, 0.f);
    for (int i = s; i < e; i++) {
        const float4* row = reinterpret_cast<const float4*>(h + (size_t)esrc[i] * D);
        float4 v = __ldg(&row[lane]);
        acc.x += v.x; acc.y += v.y; acc.z += v.z; acc.w += v.w;
    }
    float inv = 1.0f / fmaxf((float)(e - s), 1.0f);
    acc.x *= inv; acc.y *= inv; acc.z *= inv; acc.w *= inv;
    reinterpret_cast<float4*>(agg + (size_t)gw * D)[lane] = acc;
}

// ---------------- mma.sync tf32 GEMM ----------------
// C[M,128] = op(A1@B1 (+ A2@B2) + bias). B weights [K=128, N=128] staged transposed
// (Bs[n][k], rna-rounded). A tiles [128m x 128k] streamed via cp.async, then
// RNA-rounded in smem (kills tf32 truncation bias, the R3 failure mode).
// 256 thr = 8 warps, warp grid 4(M)x2(N), warp tile 32x64.

__device__ __forceinline__ void cp_a_tile(float* Asm, const float* __restrict__ A,
                                          int m0, int M, int t) {
    uint32_t sb = smem_u32(Asm);
    #pragma unroll
    for (int j = 0; j < 16; j++) {
        int lin = t + 256 * j;
        int row = lin >> 5;      // 0..127
        int c4  = lin & 31;      // 16B chunk 0..31
        int gm  = m0 + row;
        if (gm < M)
            CP_ASYNC16(sb + (uint32_t)(row * AS + c4 * 4) * 4,
                       A + (size_t)gm * D + c4 * 4);
    }
}

// RNA-round a staged A tile in place (call after CP_WAIT0 + syncthreads).
__device__ __forceinline__ void round_a_tile(float* Asm, int t) {
    #pragma unroll
    for (int j = 0; j < 16; j++) {
        int lin = t + 256 * j;
        int row = lin >> 5;
        int c4  = lin & 31;
        float4* p = reinterpret_cast<float4*>(Asm + row * AS + c4 * 4);
        float4 v = *p;
        uint4 r;
        r.x = f2tf(v.x); r.y = f2tf(v.y); r.z = f2tf(v.z); r.w = f2tf(v.w);
        *reinterpret_cast<uint4*>(p) = r;
    }
}

// Load weight W[k][n] transposed+rounded into Bs[n][k] (one-time).
__device__ __forceinline__ void load_b_tile(float* Bsm, const float* __restrict__ W, int t) {
    uint32_t* B32 = reinterpret_cast<uint32_t*>(Bsm);
    #pragma unroll 4
    for (int j = 0; j < 64; j++) {
        int lin = t + 256 * j;
        int k = lin >> 7;        // 0..127
        int n = lin & 127;       // 0..127
        B32[n * AS + k] = f2tf(W[(size_t)k * D + n]);
    }
}

// acc[mt][nt][4] += Asm(128x128) @ Bsm(stored [n][k])^T restricted to this warp's 32x64 tile
__device__ __forceinline__ void mma_compute(float acc[2][8][4], const float* Asm,
                                            const float* Bsm, int wm, int wn,
                                            int g, int tig) {
    const uint32_t* A32 = reinterpret_cast<const uint32_t*>(Asm);
    const uint32_t* B32 = reinterpret_cast<const uint32_t*>(Bsm);
    #pragma unroll
    for (int k0 = 0; k0 < D; k0 += 8) {
        uint32_t a[2][4];
        #pragma unroll
        for (int mt = 0; mt < 2; mt++) {
            int r = wm + mt * 16 + g;
            a[mt][0] = A32[r * AS + k0 + tig];
            a[mt][1] = A32[(r + 8) * AS + k0 + tig];
            a[mt][2] = A32[r * AS + k0 + tig + 4];
            a[mt][3] = A32[(r + 8) * AS + k0 + tig + 4];
        }
        #pragma unroll
        for (int nt = 0; nt < 8; nt++) {
            int c = wn + nt * 8 + g;
            uint32_t b0 = B32[c * AS + k0 + tig];
            uint32_t b1 = B32[c * AS + k0 + tig + 4];
            mma_tf32(acc[0][nt], a[0], b0, b1);
            mma_tf32(acc[1][nt], a[1], b0, b1);
        }
    }
}

template <int RELU>
__device__ __forceinline__ void epilogue(float acc[2][8][4], float* __restrict__ C,
                                         const float* s_bias, int m0, int M,
                                         int wm, int wn, int g, int tig) {
    #pragma unroll
    for (int mt = 0; mt < 2; mt++) {
        #pragma unroll
        for (int half = 0; half < 2; half++) {
            int gm = m0 + wm + mt * 16 + g + half * 8;
            if (gm >= M) continue;
            #pragma unroll
            for (int nt = 0; nt < 8; nt++) {
                int c = wn + nt * 8 + 2 * tig;
                float x = acc[mt][nt][half * 2 + 0] + s_bias[c];
                float y = acc[mt][nt][half * 2 + 1] + s_bias[c + 1];
                if (RELU) { x = fmaxf(x, 0.f); y = fmaxf(y, 0.f); }
                float2 v = make_float2(x, y);
                *reinterpret_cast<float2*>(C + (size_t)gm * D + c) = v;
            }
        }
    }
}

template <int RELU, int DUAL>
__global__ void __launch_bounds__(256, 1)
tc_gemm_kernel(const float* __restrict__ A1, const float* __restrict__ B1,
               const float* __restrict__ A2, const float* __restrict__ B2,
               const float* __restrict__ bias1, const float* __restrict__ bias2,
               float* __restrict__ C, int M) {
    extern __shared__ float dsm[];
    __shared__ float s_bias[D];

    // smem: [B1][B2 or Abuf1][Abuf0]  (each 128*AS floats)
    float* Bs1 = dsm;
    float* Bs2 = Bs1 + 128 * AS;   // DUAL: second weight; non-DUAL: A buffer 1
    float* Ab0 = Bs2 + 128 * AS;
    float* Ab1 = Bs2;              // alias, non-DUAL only

    const int t    = threadIdx.x;
    const int w    = t >> 5;
    const int lane = t & 31;
    const int g    = lane >> 2;
    const int tig  = lane & 3;
    const int wm   = (w >> 1) * 32;
    const int wn   = (w & 1) * 64;

    if (t < D) s_bias[t] = bias1[t] + (DUAL ? bias2[t] : 0.f);
    load_b_tile(Bs1, B1, t);
    if (DUAL) load_b_tile(Bs2, B2, t);

    const int ntiles = (M + 127) >> 7;
    float acc[2][8][4];

    if (!DUAL) {
        int tile = blockIdx.x;
        if (tile < ntiles) cp_a_tile(Ab0, A1, tile << 7, M, t);
        CP_COMMIT();
        __syncthreads();  // B ready
        int idx = 0;
        for (; tile < ntiles; tile += gridDim.x, idx++) {
            float* cur = (idx & 1) ? Ab1 : Ab0;
            float* nxt = (idx & 1) ? Ab0 : Ab1;
            CP_WAIT0();
            __syncthreads();
            int nt2 = tile + gridDim.x;
            if (nt2 < ntiles) cp_a_tile(nxt, A1, nt2 << 7, M, t);
            CP_COMMIT();
            round_a_tile(cur, t);   // RNA-round this tile (kills truncation bias)
            __syncthreads();
            #pragma unroll
            for (int i = 0; i < 2; i++)
                #pragma unroll
                for (int j = 0; j < 8; j++)
                    #pragma unroll
                    for (int q = 0; q < 4; q++) acc[i][j][q] = 0.f;
            mma_compute(acc, cur, Bs1, wm, wn, g, tig);
            epilogue<RELU>(acc, C, s_bias, tile << 7, M, wm, wn, g, tig);
            __syncthreads();  // all warps done with cur before it is refilled
        }
    } else {
        __syncthreads();  // B1/B2 ready
        for (int tile = blockIdx.x; tile < ntiles; tile += gridDim.x) {
            cp_a_tile(Ab0, A1, tile << 7, M, t);
            CP_COMMIT(); CP_WAIT0();
            __syncthreads();
            round_a_tile(Ab0, t);
            __syncthreads();
            #pragma unroll
            for (int i = 0; i < 2; i++)
                #pragma unroll
                for (int j = 0; j < 8; j++)
                    #pragma unroll
                    for (int q = 0; q < 4; q++) acc[i][j][q] = 0.f;
            mma_compute(acc, Ab0, Bs1, wm, wn, g, tig);
            __syncthreads();  // done reading Ab0
            cp_a_tile(Ab0, A2, tile << 7, M, t);
            CP_COMMIT(); CP_WAIT0();
            __syncthreads();
            round_a_tile(Ab0, t);
            __syncthreads();
            mma_compute(acc, Ab0, Bs2, wm, wn, g, tig);
            epilogue<RELU>(acc, C, s_bias, tile << 7, M, wm, wn, g, tig);
            __syncthreads();
        }
    }
}

// ---------------- launch ----------------
extern "C" void kernel_launch(void* const* d_in, const int* in_sizes, int n_in,
                              void* d_out, int out_size) {
    const float* features = (const float*)d_in[0];
    const int*   src0     = (const int*)d_in[1];
    const int*   dst0     = (const int*)d_in[2];
    const int*   src1     = (const int*)d_in[3];
    const int*   dst1     = (const int*)d_in[4];
    const float* W_init   = (const float*)d_in[5];
    const float* b_init   = (const float*)d_in[6];
    const float* W_self   = (const float*)d_in[7];
    const float* b_self   = (const float*)d_in[8];
    const float* W_neigh  = (const float*)d_in[9];
    const float* b_neigh  = (const float*)d_in[10];
    float*       out      = (float*)d_out;

    float *h0, *h1, *agg0, *agg1;
    int *off0, *esrc0, *off1, *esrc1;
    cudaGetSymbolAddress((void**)&h0, g_h0);
    cudaGetSymbolAddress((void**)&h1, g_h1);
    cudaGetSymbolAddress((void**)&agg0, g_agg0);
    cudaGetSymbolAddress((void**)&agg1, g_agg1);
    cudaGetSymbolAddress((void**)&off0, g_off0);
    cudaGetSymbolAddress((void**)&esrc0, g_esrc0);
    cudaGetSymbolAddress((void**)&off1, g_off1);
    cudaGetSymbolAddress((void**)&esrc1, g_esrc1);

    const int SMEM_BYTES = 3 * 128 * AS * 4;  // 202752
    cudaFuncSetAttribute(tc_gemm_kernel<1, 0>, cudaFuncAttributeMaxDynamicSharedMemorySize, SMEM_BYTES);
    cudaFuncSetAttribute(tc_gemm_kernel<1, 1>, cudaFuncAttributeMaxDynamicSharedMemorySize, SMEM_BYTES);
    cudaFuncSetAttribute(tc_gemm_kernel<0, 1>, cudaFuncAttributeMaxDynamicSharedMemorySize, SMEM_BYTES);

    // --- CSR build for both graphs ---
    zero_counts_kernel<<<(NDST0 + 255) / 256, 256>>>();
    hist_kernel<<<(E0 + 255) / 256, 256>>>(dst0, dst1);
    scan_kernel<<<2, 1024>>>();
    scatter_kernel<<<(E0 + 255) / 256, 256>>>(src0, dst0, src1, dst1);

    // --- layer 0: h0 = relu(features @ W_init + b_init) ---
    tc_gemm_kernel<1, 0><<<148, 256, SMEM_BYTES>>>(
        features, W_init, nullptr, nullptr, b_init, nullptr, h0, NSRC0);

    // --- block 0 mean aggregation ---
    aggregate_kernel<<<(NDST0 * 32 + 255) / 256, 256>>>(h0, off0, esrc0, agg0, NDST0);

    // --- layer 1: h1 = relu(h0[:50000]@W_self + agg0@W_neigh + biases) ---
    tc_gemm_kernel<1, 1><<<148, 256, SMEM_BYTES>>>(
        h0, W_self, agg0, W_neigh, b_self, b_neigh, h1, NDST0);

    // --- block 1 mean aggregation ---
    aggregate_kernel<<<(NDST1 * 32 + 255) / 256, 256>>>(h1, off1, esrc1, agg1, NDST1);

    // --- layer 2 (no relu) ---
    tc_gemm_kernel<0, 1><<<79, 256, SMEM_BYTES>>>(
        h1, W_self, agg1, W_neigh, b_self, b_neigh, out, NDST1);
}

// round 5
// speedup vs baseline: 2.1015x; 1.3391x over previous
#include <cuda_runtime.h>
#include <cuda_bf16.h>
#include <cstdint>
#include <cstddef>

// Problem constants (fixed by the reference)
#define NSRC0 200000
#define NDST0 50000
#define NDST1 10000
#define E0    800000
#define E1    160000
#define D     128

#define AS 132  // padded smem row stride (floats): bank = (4*row + col) % 32 -> conflict-free frags

#define NB0 49  // ceil(50000/1024)
#define NB1 10  // ceil(10000/1024)

// ---------------- device scratch (static globals; no allocation) ----------------
__device__ float g_h0[(size_t)NSRC0 * D];
__device__ float g_h1[(size_t)NDST0 * D];
__device__ float g_agg0[(size_t)NDST0 * D];
__device__ float g_agg1[(size_t)NDST1 * D];

__device__ int g_cnt0[NDST0];
__device__ int g_off0[NDST0 + 1];
__device__ int g_cur0[NDST0];
__device__ int g_esrc0[E0];

__device__ int g_cnt1[NDST1];
__device__ int g_off1[NDST1 + 1];
__device__ int g_cur1[NDST1];
__device__ int g_esrc1[E1];

__device__ int g_bsum[NB0 + NB1];
__device__ int g_bbase[NB0 + NB1];

// ---------------- helpers ----------------
__device__ __forceinline__ uint32_t smem_u32(const void* p) {
    uint32_t a;
    asm("{ .reg .u64 t; cvta.to.shared.u64 t, %1; cvt.u32.u64 %0, t; }" : "=r"(a) : "l"(p));
    return a;
}
__device__ __forceinline__ uint32_t f2tf(float f) {
    uint32_t r;
    asm("cvt.rna.tf32.f32 %0, %1;" : "=r"(r) : "f"(f));
    return r;
}
#define CP_ASYNC16(dst, src) \
    asm volatile("cp.async.cg.shared.global [%0], [%1], 16;" :: "r"(dst), "l"(src) : "memory")
#define CP_COMMIT() asm volatile("cp.async.commit_group;" ::: "memory")
#define CP_WAIT0()  asm volatile("cp.async.wait_group 0;" ::: "memory")

__device__ __forceinline__ void mma_tf32(float d[4], const uint32_t a[4], uint32_t b0, uint32_t b1) {
    asm volatile(
        "mma.sync.aligned.m16n8k8.row.col.f32.tf32.tf32.f32 "
        "{%0,%1,%2,%3}, {%4,%5,%6,%7}, {%8,%9}, {%0,%1,%2,%3};"
        : "+f"(d[0]), "+f"(d[1]), "+f"(d[2]), "+f"(d[3])
        : "r"(a[0]), "r"(a[1]), "r"(a[2]), "r"(a[3]), "r"(b0), "r"(b1));
}

// ---------------- CSR build ----------------
__global__ void zero_counts_kernel() {
    int i = blockIdx.x * blockDim.x + threadIdx.x;
    if (i < NDST0) g_cnt0[i] = 0;
    if (i < NDST1) g_cnt1[i] = 0;
}
__global__ void hist_kernel(const int* __restrict__ dst0, const int* __restrict__ dst1) {
    int i = blockIdx.x * blockDim.x + threadIdx.x;
    if (i < E0) atomicAdd(&g_cnt0[dst0[i]], 1);
    if (i < E1) atomicAdd(&g_cnt1[dst1[i]], 1);
}

// Phase 1: per-block exclusive scan of counts into off (sans base); block totals to g_bsum.
__global__ void scan_blocks_kernel() {
    __shared__ int sums[1024];
    const int b = blockIdx.x;
    const int tid = threadIdx.x;
    const int graph = (b < NB0) ? 0 : 1;
    const int blk = graph ? (b - NB0) : b;
    const int n = graph ? NDST1 : NDST0;
    const int* cnt = graph ? g_cnt1 : g_cnt0;
    int* off = graph ? g_off1 : g_off0;

    const int i = blk * 1024 + tid;
    const int v = (i < n) ? cnt[i] : 0;
    sums[tid] = v;
    __syncthreads();
    #pragma unroll
    for (int d = 1; d < 1024; d <<= 1) {
        int x = (tid >= d) ? sums[tid - d] : 0;
        __syncthreads();
        sums[tid] += x;
        __syncthreads();
    }
    if (i < n) off[i] = sums[tid] - v;
    if (tid == 1023) g_bsum[b] = sums[1023];
}

// Phase 2: tiny sequential scan of block totals (per graph). 1 block, 1 warp.
__global__ void scan_tops_kernel() {
    if (threadIdx.x == 0) {
        int run = 0;
        for (int b = 0; b < NB0; b++) { g_bbase[b] = run; run += g_bsum[b]; }
        g_off0[NDST0] = E0;
        run = 0;
        for (int b = NB0; b < NB0 + NB1; b++) { g_bbase[b] = run; run += g_bsum[b]; }
        g_off1[NDST1] = E1;
    }
}

// Phase 3: add block bases; init cursors.
__global__ void scan_apply_kernel() {
    const int b = blockIdx.x;
    const int tid = threadIdx.x;
    const int graph = (b < NB0) ? 0 : 1;
    const int blk = graph ? (b - NB0) : b;
    const int n = graph ? NDST1 : NDST0;
    int* off = graph ? g_off1 : g_off0;
    int* cur = graph ? g_cur1 : g_cur0;
    const int base = g_bbase[b];
    const int i = blk * 1024 + tid;
    if (i < n) {
        int o = off[i] + base;
        off[i] = o;
        cur[i] = o;
    }
}

__global__ void scatter_kernel(const int* __restrict__ src0, const int* __restrict__ dst0,
                               const int* __restrict__ src1, const int* __restrict__ dst1) {
    int i = blockIdx.x * blockDim.x + threadIdx.x;
    if (i < E0) { int pos = atomicAdd(&g_cur0[dst0[i]], 1); g_esrc0[pos] = src0[i]; }
    if (i < E1) { int pos = atomicAdd(&g_cur1[dst1[i]], 1); g_esrc1[pos] = src1[i]; }
}

// ---------------- mean aggregation: one warp per destination node ----------------
__global__ void aggregate_kernel(const float* __restrict__ h, const int* __restrict__ off,
                                 const int* __restrict__ esrc, float* __restrict__ agg,
                                 int ndst) {
    int gw = (blockIdx.x * blockDim.x + threadIdx.x) >> 5;
    int lane = threadIdx.x & 31;
    if (gw >= ndst) return;
    int s = off[gw], e = off[gw + 1];
    float4 acc = make_float4(0.f, 0.f, 0.f, 0.f);
    for (int i = s; i < e; i++) {
        const float4* row = reinterpret_cast<const float4*>(h + (size_t)esrc[i] * D);
        float4 v = __ldg(&row[lane]);
        acc.x += v.x; acc.y += v.y; acc.z += v.z; acc.w += v.w;
    }
    float inv = 1.0f / fmaxf((float)(e - s), 1.0f);
    acc.x *= inv; acc.y *= inv; acc.z *= inv; acc.w *= inv;
    reinterpret_cast<float4*>(agg + (size_t)gw * D)[lane] = acc;
}

// ---------------- mma.sync tf32 GEMM (proven in R4) ----------------
__device__ __forceinline__ void cp_a_tile(float* Asm, const float* __restrict__ A,
                                          int m0, int M, int t) {
    uint32_t sb = smem_u32(Asm);
    #pragma unroll
    for (int j = 0; j < 16; j++) {
        int lin = t + 256 * j;
        int row = lin >> 5;
        int c4  = lin & 31;
        int gm  = m0 + row;
        if (gm < M)
            CP_ASYNC16(sb + (uint32_t)(row * AS + c4 * 4) * 4,
                       A + (size_t)gm * D + c4 * 4);
    }
}

__device__ __forceinline__ void round_a_tile(float* Asm, int t) {
    #pragma unroll
    for (int j = 0; j < 16; j++) {
        int lin = t + 256 * j;
        int row = lin >> 5;
        int c4  = lin & 31;
        float4* p = reinterpret_cast<float4*>(Asm + row * AS + c4 * 4);
        float4 v = *p;
        uint4 r;
        r.x = f2tf(v.x); r.y = f2tf(v.y); r.z = f2tf(v.z); r.w = f2tf(v.w);
        *reinterpret_cast<uint4*>(p) = r;
    }
}

__device__ __forceinline__ void load_b_tile(float* Bsm, const float* __restrict__ W, int t) {
    uint32_t* B32 = reinterpret_cast<uint32_t*>(Bsm);
    #pragma unroll 4
    for (int j = 0; j < 64; j++) {
        int lin = t + 256 * j;
        int k = lin >> 7;
        int n = lin & 127;
        B32[n * AS + k] = f2tf(W[(size_t)k * D + n]);
    }
}

__device__ __forceinline__ void mma_compute(float acc[2][8][4], const float* Asm,
                                            const float* Bsm, int wm, int wn,
                                            int g, int tig) {
    const uint32_t* A32 = reinterpret_cast<const uint32_t*>(Asm);
    const uint32_t* B32 = reinterpret_cast<const uint32_t*>(Bsm);
    #pragma unroll
    for (int k0 = 0; k0 < D; k0 += 8) {
        uint32_t a[2][4];
        #pragma unroll
        for (int mt = 0; mt < 2; mt++) {
            int r = wm + mt * 16 + g;
            a[mt][0] = A32[r * AS + k0 + tig];
            a[mt][1] = A32[(r + 8) * AS + k0 + tig];
            a[mt][2] = A32[r * AS + k0 + tig + 4];
            a[mt][3] = A32[(r + 8) * AS + k0 + tig + 4];
        }
        #pragma unroll
        for (int nt = 0; nt < 8; nt++) {
            int c = wn + nt * 8 + g;
            uint32_t b0 = B32[c * AS + k0 + tig];
            uint32_t b1 = B32[c * AS + k0 + tig + 4];
            mma_tf32(acc[0][nt], a[0], b0, b1);
            mma_tf32(acc[1][nt], a[1], b0, b1);
        }
    }
}

template <int RELU>
__device__ __forceinline__ void epilogue(float acc[2][8][4], float* __restrict__ C,
                                         const float* s_bias, int m0, int M,
                                         int wm, int wn, int g, int tig) {
    #pragma unroll
    for (int mt = 0; mt < 2; mt++) {
        #pragma unroll
        for (int half = 0; half < 2; half++) {
            int gm = m0 + wm + mt * 16 + g + half * 8;
            if (gm >= M) continue;
            #pragma unroll
            for (int nt = 0; nt < 8; nt++) {
                int c = wn + nt * 8 + 2 * tig;
                float x = acc[mt][nt][half * 2 + 0] + s_bias[c];
                float y = acc[mt][nt][half * 2 + 1] + s_bias[c + 1];
                if (RELU) { x = fmaxf(x, 0.f); y = fmaxf(y, 0.f); }
                float2 v = make_float2(x, y);
                *reinterpret_cast<float2*>(C + (size_t)gm * D + c) = v;
            }
        }
    }
}

template <int RELU, int DUAL>
__global__ void __launch_bounds__(256, 1)
tc_gemm_kernel(const float* __restrict__ A1, const float* __restrict__ B1,
               const float* __restrict__ A2, const float* __restrict__ B2,
               const float* __restrict__ bias1, const float* __restrict__ bias2,
               float* __restrict__ C, int M) {
    extern __shared__ float dsm[];
    __shared__ float s_bias[D];

    float* Bs1 = dsm;
    float* Bs2 = Bs1 + 128 * AS;
    float* Ab0 = Bs2 + 128 * AS;
    float* Ab1 = Bs2;  // alias, non-DUAL only

    const int t    = threadIdx.x;
    const int w    = t >> 5;
    const int lane = t & 31;
    const int g    = lane >> 2;
    const int tig  = lane & 3;
    const int wm   = (w >> 1) * 32;
    const int wn   = (w & 1) * 64;

    if (t < D) s_bias[t] = bias1[t] + (DUAL ? bias2[t] : 0.f);
    load_b_tile(Bs1, B1, t);
    if (DUAL) load_b_tile(Bs2, B2, t);

    const int ntiles = (M + 127) >> 7;
    float acc[2][8][4];

    if (!DUAL) {
        int tile = blockIdx.x;
        if (tile < ntiles) cp_a_tile(Ab0, A1, tile << 7, M, t);
        CP_COMMIT();
        __syncthreads();
        int idx = 0;
        for (; tile < ntiles; tile += gridDim.x, idx++) {
            float* cur = (idx & 1) ? Ab1 : Ab0;
            float* nxt = (idx & 1) ? Ab0 : Ab1;
            CP_WAIT0();
            __syncthreads();
            int nt2 = tile + gridDim.x;
            if (nt2 < ntiles) cp_a_tile(nxt, A1, nt2 << 7, M, t);
            CP_COMMIT();
            round_a_tile(cur, t);
            __syncthreads();
            #pragma unroll
            for (int i = 0; i < 2; i++)
                #pragma unroll
                for (int j = 0; j < 8; j++)
                    #pragma unroll
                    for (int q = 0; q < 4; q++) acc[i][j][q] = 0.f;
            mma_compute(acc, cur, Bs1, wm, wn, g, tig);
            epilogue<RELU>(acc, C, s_bias, tile << 7, M, wm, wn, g, tig);
            __syncthreads();
        }
    } else {
        __syncthreads();
        for (int tile = blockIdx.x; tile < ntiles; tile += gridDim.x) {
            cp_a_tile(Ab0, A1, tile << 7, M, t);
            CP_COMMIT(); CP_WAIT0();
            __syncthreads();
            round_a_tile(Ab0, t);
            __syncthreads();
            #pragma unroll
            for (int i = 0; i < 2; i++)
                #pragma unroll
                for (int j = 0; j < 8; j++)
                    #pragma unroll
                    for (int q = 0; q < 4; q++) acc[i][j][q] = 0.f;
            mma_compute(acc, Ab0, Bs1, wm, wn, g, tig);
            __syncthreads();
            cp_a_tile(Ab0, A2, tile << 7, M, t);
            CP_COMMIT(); CP_WAIT0();
            __syncthreads();
            round_a_tile(Ab0, t);
            __syncthreads();
            mma_compute(acc, Ab0, Bs2, wm, wn, g, tig);
            epilogue<RELU>(acc, C, s_bias, tile << 7, M, wm, wn, g, tig);
            __syncthreads();
        }
    }
}

// ---------------- launch ----------------
extern "C" void kernel_launch(void* const* d_in, const int* in_sizes, int n_in,
                              void* d_out, int out_size) {
    const float* features = (const float*)d_in[0];
    const int*   src0     = (const int*)d_in[1];
    const int*   dst0     = (const int*)d_in[2];
    const int*   src1     = (const int*)d_in[3];
    const int*   dst1     = (const int*)d_in[4];
    const float* W_init   = (const float*)d_in[5];
    const float* b_init   = (const float*)d_in[6];
    const float* W_self   = (const float*)d_in[7];
    const float* b_self   = (const float*)d_in[8];
    const float* W_neigh  = (const float*)d_in[9];
    const float* b_neigh  = (const float*)d_in[10];
    float*       out      = (float*)d_out;

    float *h0, *h1, *agg0, *agg1;
    int *off0, *esrc0, *off1, *esrc1;
    cudaGetSymbolAddress((void**)&h0, g_h0);
    cudaGetSymbolAddress((void**)&h1, g_h1);
    cudaGetSymbolAddress((void**)&agg0, g_agg0);
    cudaGetSymbolAddress((void**)&agg1, g_agg1);
    cudaGetSymbolAddress((void**)&off0, g_off0);
    cudaGetSymbolAddress((void**)&esrc0, g_esrc0);
    cudaGetSymbolAddress((void**)&off1, g_off1);
    cudaGetSymbolAddress((void**)&esrc1, g_esrc1);

    const int SMEM_BYTES = 3 * 128 * AS * 4;  // 202752
    static bool s_init = false;
    static cudaStream_t s_side;
    static cudaEvent_t ev_fork, ev_csr;
    if (!s_init) {
        // First call is the (non-captured) correctness run: safe place for one-time setup.
        cudaFuncSetAttribute(tc_gemm_kernel<1, 0>, cudaFuncAttributeMaxDynamicSharedMemorySize, SMEM_BYTES);
        cudaFuncSetAttribute(tc_gemm_kernel<1, 1>, cudaFuncAttributeMaxDynamicSharedMemorySize, SMEM_BYTES);
        cudaFuncSetAttribute(tc_gemm_kernel<0, 1>, cudaFuncAttributeMaxDynamicSharedMemorySize, SMEM_BYTES);
        cudaStreamCreateWithFlags(&s_side, cudaStreamNonBlocking);
        cudaEventCreateWithFlags(&ev_fork, cudaEventDisableTiming);
        cudaEventCreateWithFlags(&ev_csr, cudaEventDisableTiming);
        s_init = true;
    }

    // ---- fork: CSR chain on side stream, GEMM1 on main stream ----
    cudaEventRecord(ev_fork, 0);
    cudaStreamWaitEvent(s_side, ev_fork, 0);

    zero_counts_kernel<<<(NDST0 + 255) / 256, 256, 0, s_side>>>();
    hist_kernel<<<(E0 + 255) / 256, 256, 0, s_side>>>(dst0, dst1);
    scan_blocks_kernel<<<NB0 + NB1, 1024, 0, s_side>>>();
    scan_tops_kernel<<<1, 32, 0, s_side>>>();
    scan_apply_kernel<<<NB0 + NB1, 1024, 0, s_side>>>();
    scatter_kernel<<<(E0 + 255) / 256, 256, 0, s_side>>>(src0, dst0, src1, dst1);
    cudaEventRecord(ev_csr, s_side);

    // --- layer 0 (main stream, concurrent with CSR build) ---
    tc_gemm_kernel<1, 0><<<148, 256, SMEM_BYTES>>>(
        features, W_init, nullptr, nullptr, b_init, nullptr, h0, NSRC0);

    // ---- join: aggregation needs both h0 and the CSR ----
    cudaStreamWaitEvent(0, ev_csr, 0);

    aggregate_kernel<<<(NDST0 * 32 + 255) / 256, 256>>>(h0, off0, esrc0, agg0, NDST0);

    tc_gemm_kernel<1, 1><<<148, 256, SMEM_BYTES>>>(
        h0, W_self, agg0, W_neigh, b_self, b_neigh, h1, NDST0);

    aggregate_kernel<<<(NDST1 * 32 + 255) / 256, 256>>>(h1, off1, esrc1, agg1, NDST1);

    tc_gemm_kernel<0, 1><<<79, 256, SMEM_BYTES>>>(
        h1, W_self, agg1, W_neigh, b_self, b_neigh, out, NDST1);
}

// round 6
// speedup vs baseline: 2.3201x; 1.1040x over previous
#include <cuda_runtime.h>
#include <cuda_bf16.h>
#include <cstdint>
#include <cstddef>

// Problem constants (fixed by the reference)
#define NSRC0 200000
#define NDST0 50000
#define NDST1 10000
#define E0    800000
#define E1    160000
#define D     128

#define AS 132  // padded smem row stride (floats): bank = (4*row + col) % 32 -> conflict-free frags

#define NB0 49  // ceil(50000/1024)
#define NB1 10  // ceil(10000/1024)

// ---------------- device scratch (static globals; no allocation) ----------------
__device__ float g_h0[(size_t)NSRC0 * D];
__device__ float g_h1[(size_t)NDST0 * D];
__device__ float g_agg0[(size_t)NDST0 * D];
__device__ float g_agg1[(size_t)NDST1 * D];

__device__ int g_cnt0[NDST0];
__device__ int g_off0[NDST0 + 1];
__device__ int g_cur0[NDST0];
__device__ int g_esrc0[E0];

__device__ int g_cnt1[NDST1];
__device__ int g_off1[NDST1 + 1];
__device__ int g_cur1[NDST1];
__device__ int g_esrc1[E1];

__device__ int g_bsum[NB0 + NB1];
__device__ int g_bbase[NB0 + NB1];

// ---------------- helpers ----------------
__device__ __forceinline__ uint32_t smem_u32(const void* p) {
    uint32_t a;
    asm("{ .reg .u64 t; cvta.to.shared.u64 t, %1; cvt.u32.u64 %0, t; }" : "=r"(a) : "l"(p));
    return a;
}
__device__ __forceinline__ uint32_t f2tf(float f) {
    uint32_t r;
    asm("cvt.rna.tf32.f32 %0, %1;" : "=r"(r) : "f"(f));
    return r;
}
#define CP_ASYNC16(dst, src) \
    asm volatile("cp.async.cg.shared.global [%0], [%1], 16;" :: "r"(dst), "l"(src) : "memory")
#define CP_COMMIT() asm volatile("cp.async.commit_group;" ::: "memory")
#define CP_WAIT0()  asm volatile("cp.async.wait_group 0;" ::: "memory")

__device__ __forceinline__ void mma_tf32(float d[4], const uint32_t a[4], uint32_t b0, uint32_t b1) {
    asm volatile(
        "mma.sync.aligned.m16n8k8.row.col.f32.tf32.tf32.f32 "
        "{%0,%1,%2,%3}, {%4,%5,%6,%7}, {%8,%9}, {%0,%1,%2,%3};"
        : "+f"(d[0]), "+f"(d[1]), "+f"(d[2]), "+f"(d[3])
        : "r"(a[0]), "r"(a[1]), "r"(a[2]), "r"(a[3]), "r"(b0), "r"(b1));
}

// ---------------- CSR build ----------------
__global__ void zero_counts_kernel() {
    int i = blockIdx.x * blockDim.x + threadIdx.x;
    if (i < NDST0) g_cnt0[i] = 0;
    if (i < NDST1) g_cnt1[i] = 0;
}
__global__ void hist_kernel(const int* __restrict__ dst0, const int* __restrict__ dst1) {
    int i = blockIdx.x * blockDim.x + threadIdx.x;
    if (i < E0) atomicAdd(&g_cnt0[dst0[i]], 1);
    if (i < E1) atomicAdd(&g_cnt1[dst1[i]], 1);
}

// Phase 1: per-block exclusive scan of counts into off (sans base); block totals to g_bsum.
__global__ void scan_blocks_kernel() {
    __shared__ int sums[1024];
    const int b = blockIdx.x;
    const int tid = threadIdx.x;
    const int graph = (b < NB0) ? 0 : 1;
    const int blk = graph ? (b - NB0) : b;
    const int n = graph ? NDST1 : NDST0;
    const int* cnt = graph ? g_cnt1 : g_cnt0;
    int* off = graph ? g_off1 : g_off0;

    const int i = blk * 1024 + tid;
    const int v = (i < n) ? cnt[i] : 0;
    sums[tid] = v;
    __syncthreads();
    #pragma unroll
    for (int d = 1; d < 1024; d <<= 1) {
        int x = (tid >= d) ? sums[tid - d] : 0;
        __syncthreads();
        sums[tid] += x;
        __syncthreads();
    }
    if (i < n) off[i] = sums[tid] - v;
    if (tid == 1023) g_bsum[b] = sums[1023];
}

// Phase 2: parallel exclusive scan of block totals (64-thread Hillis-Steele per graph).
__global__ void scan_tops_kernel() {
    __shared__ int s[64];
    const int t = threadIdx.x;
    // graph 0: 49 totals
    s[t] = (t < NB0) ? g_bsum[t] : 0;
    __syncthreads();
    #pragma unroll
    for (int d = 1; d < 64; d <<= 1) {
        int x = (t >= d) ? s[t - d] : 0;
        __syncthreads();
        s[t] += x;
        __syncthreads();
    }
    if (t < NB0) g_bbase[t] = s[t] - g_bsum[t];
    __syncthreads();
    // graph 1: 10 totals
    s[t] = (t < NB1) ? g_bsum[NB0 + t] : 0;
    __syncthreads();
    #pragma unroll
    for (int d = 1; d < 64; d <<= 1) {
        int x = (t >= d) ? s[t - d] : 0;
        __syncthreads();
        s[t] += x;
        __syncthreads();
    }
    if (t < NB1) g_bbase[NB0 + t] = s[t] - g_bsum[NB0 + t];
    if (t == 0) { g_off0[NDST0] = E0; g_off1[NDST1] = E1; }
}

// Phase 3: add block bases; init cursors.
__global__ void scan_apply_kernel() {
    const int b = blockIdx.x;
    const int tid = threadIdx.x;
    const int graph = (b < NB0) ? 0 : 1;
    const int blk = graph ? (b - NB0) : b;
    const int n = graph ? NDST1 : NDST0;
    int* off = graph ? g_off1 : g_off0;
    int* cur = graph ? g_cur1 : g_cur0;
    const int base = g_bbase[b];
    const int i = blk * 1024 + tid;
    if (i < n) {
        int o = off[i] + base;
        off[i] = o;
        cur[i] = o;
    }
}

__global__ void scatter_kernel(const int* __restrict__ src0, const int* __restrict__ dst0,
                               const int* __restrict__ src1, const int* __restrict__ dst1) {
    int i = blockIdx.x * blockDim.x + threadIdx.x;
    if (i < E0) { int pos = atomicAdd(&g_cur0[dst0[i]], 1); g_esrc0[pos] = src0[i]; }
    if (i < E1) { int pos = atomicAdd(&g_cur1[dst1[i]], 1); g_esrc1[pos] = src1[i]; }
}

// ---------------- mean aggregation: one warp per destination node, 2x unrolled ----------------
__global__ void aggregate_kernel(const float* __restrict__ h, const int* __restrict__ off,
                                 const int* __restrict__ esrc, float* __restrict__ agg,
                                 int ndst) {
    int gw = (blockIdx.x * blockDim.x + threadIdx.x) >> 5;
    int lane = threadIdx.x & 31;
    if (gw >= ndst) return;
    int s = off[gw], e = off[gw + 1];
    float4 acc = make_float4(0.f, 0.f, 0.f, 0.f);
    float4 acc2 = make_float4(0.f, 0.f, 0.f, 0.f);
    int i = s;
    for (; i + 2 <= e; i += 2) {
        const float4* r0 = reinterpret_cast<const float4*>(h + (size_t)esrc[i] * D);
        const float4* r1 = reinterpret_cast<const float4*>(h + (size_t)esrc[i + 1] * D);
        float4 v0 = __ldg(&r0[lane]);
        float4 v1 = __ldg(&r1[lane]);
        acc.x += v0.x; acc.y += v0.y; acc.z += v0.z; acc.w += v0.w;
        acc2.x += v1.x; acc2.y += v1.y; acc2.z += v1.z; acc2.w += v1.w;
    }
    if (i < e) {
        const float4* r0 = reinterpret_cast<const float4*>(h + (size_t)esrc[i] * D);
        float4 v0 = __ldg(&r0[lane]);
        acc.x += v0.x; acc.y += v0.y; acc.z += v0.z; acc.w += v0.w;
    }
    acc.x += acc2.x; acc.y += acc2.y; acc.z += acc2.z; acc.w += acc2.w;
    float inv = 1.0f / fmaxf((float)(e - s), 1.0f);
    acc.x *= inv; acc.y *= inv; acc.z *= inv; acc.w *= inv;
    reinterpret_cast<float4*>(agg + (size_t)gw * D)[lane] = acc;
}

// ---------------- mma.sync tf32 GEMM ----------------
// Single-A double-buffered persistent kernel.
// ADDC=0: C = maybe_relu(A@B + bias)           (RELU only used with ADDC)
// ADDC=1: C = maybe_relu(C + A@B + bias)       (accumulate into self-partial)
__device__ __forceinline__ void cp_a_tile(float* Asm, const float* __restrict__ A,
                                          int m0, int M, int t) {
    uint32_t sb = smem_u32(Asm);
    #pragma unroll
    for (int j = 0; j < 16; j++) {
        int lin = t + 256 * j;
        int row = lin >> 5;
        int c4  = lin & 31;
        int gm  = m0 + row;
        if (gm < M)
            CP_ASYNC16(sb + (uint32_t)(row * AS + c4 * 4) * 4,
                       A + (size_t)gm * D + c4 * 4);
    }
}

__device__ __forceinline__ void round_a_tile(float* Asm, int t) {
    #pragma unroll
    for (int j = 0; j < 16; j++) {
        int lin = t + 256 * j;
        int row = lin >> 5;
        int c4  = lin & 31;
        float4* p = reinterpret_cast<float4*>(Asm + row * AS + c4 * 4);
        float4 v = *p;
        uint4 r;
        r.x = f2tf(v.x); r.y = f2tf(v.y); r.z = f2tf(v.z); r.w = f2tf(v.w);
        *reinterpret_cast<uint4*>(p) = r;
    }
}

__device__ __forceinline__ void load_b_tile(float* Bsm, const float* __restrict__ W, int t) {
    uint32_t* B32 = reinterpret_cast<uint32_t*>(Bsm);
    #pragma unroll 4
    for (int j = 0; j < 64; j++) {
        int lin = t + 256 * j;
        int k = lin >> 7;
        int n = lin & 127;
        B32[n * AS + k] = f2tf(W[(size_t)k * D + n]);
    }
}

__device__ __forceinline__ void mma_compute(float acc[2][8][4], const float* Asm,
                                            const float* Bsm, int wm, int wn,
                                            int g, int tig) {
    const uint32_t* A32 = reinterpret_cast<const uint32_t*>(Asm);
    const uint32_t* B32 = reinterpret_cast<const uint32_t*>(Bsm);
    #pragma unroll
    for (int k0 = 0; k0 < D; k0 += 8) {
        uint32_t a[2][4];
        #pragma unroll
        for (int mt = 0; mt < 2; mt++) {
            int r = wm + mt * 16 + g;
            a[mt][0] = A32[r * AS + k0 + tig];
            a[mt][1] = A32[(r + 8) * AS + k0 + tig];
            a[mt][2] = A32[r * AS + k0 + tig + 4];
            a[mt][3] = A32[(r + 8) * AS + k0 + tig + 4];
        }
        #pragma unroll
        for (int nt = 0; nt < 8; nt++) {
            int c = wn + nt * 8 + g;
            uint32_t b0 = B32[c * AS + k0 + tig];
            uint32_t b1 = B32[c * AS + k0 + tig + 4];
            mma_tf32(acc[0][nt], a[0], b0, b1);
            mma_tf32(acc[1][nt], a[1], b0, b1);
        }
    }
}

template <int RELU, int ADDC>
__device__ __forceinline__ void epilogue(float acc[2][8][4], float* __restrict__ C,
                                         const float* s_bias, int m0, int M,
                                         int wm, int wn, int g, int tig) {
    #pragma unroll
    for (int mt = 0; mt < 2; mt++) {
        #pragma unroll
        for (int half = 0; half < 2; half++) {
            int gm = m0 + wm + mt * 16 + g + half * 8;
            if (gm >= M) continue;
            #pragma unroll
            for (int nt = 0; nt < 8; nt++) {
                int c = wn + nt * 8 + 2 * tig;
                float x = acc[mt][nt][half * 2 + 0] + s_bias[c];
                float y = acc[mt][nt][half * 2 + 1] + s_bias[c + 1];
                if (ADDC) {
                    float2 pv = *reinterpret_cast<const float2*>(C + (size_t)gm * D + c);
                    x += pv.x; y += pv.y;
                }
                if (RELU) { x = fmaxf(x, 0.f); y = fmaxf(y, 0.f); }
                float2 v = make_float2(x, y);
                *reinterpret_cast<float2*>(C + (size_t)gm * D + c) = v;
            }
        }
    }
}

template <int RELU, int ADDC>
__global__ void __launch_bounds__(256, 1)
tc_gemm_kernel(const float* __restrict__ A1, const float* __restrict__ B1,
               const float* __restrict__ bias1, float* __restrict__ C, int M) {
    extern __shared__ float dsm[];
    __shared__ float s_bias[D];

    float* Bs1 = dsm;
    float* Ab0 = Bs1 + 128 * AS;
    float* Ab1 = Ab0 + 128 * AS;

    const int t    = threadIdx.x;
    const int w    = t >> 5;
    const int lane = t & 31;
    const int g    = lane >> 2;
    const int tig  = lane & 3;
    const int wm   = (w >> 1) * 32;
    const int wn   = (w & 1) * 64;

    if (t < D) s_bias[t] = bias1[t];
    load_b_tile(Bs1, B1, t);

    const int ntiles = (M + 127) >> 7;
    float acc[2][8][4];

    int tile = blockIdx.x;
    if (tile < ntiles) cp_a_tile(Ab0, A1, tile << 7, M, t);
    CP_COMMIT();
    __syncthreads();
    int idx = 0;
    for (; tile < ntiles; tile += gridDim.x, idx++) {
        float* cur = (idx & 1) ? Ab1 : Ab0;
        float* nxt = (idx & 1) ? Ab0 : Ab1;
        CP_WAIT0();
        __syncthreads();
        int nt2 = tile + gridDim.x;
        if (nt2 < ntiles) cp_a_tile(nxt, A1, nt2 << 7, M, t);
        CP_COMMIT();
        round_a_tile(cur, t);
        __syncthreads();
        #pragma unroll
        for (int i = 0; i < 2; i++)
            #pragma unroll
            for (int j = 0; j < 8; j++)
                #pragma unroll
                for (int q = 0; q < 4; q++) acc[i][j][q] = 0.f;
        mma_compute(acc, cur, Bs1, wm, wn, g, tig);
        epilogue<RELU, ADDC>(acc, C, s_bias, tile << 7, M, wm, wn, g, tig);
        __syncthreads();
    }
}

// ---------------- launch ----------------
extern "C" void kernel_launch(void* const* d_in, const int* in_sizes, int n_in,
                              void* d_out, int out_size) {
    const float* features = (const float*)d_in[0];
    const int*   src0     = (const int*)d_in[1];
    const int*   dst0     = (const int*)d_in[2];
    const int*   src1     = (const int*)d_in[3];
    const int*   dst1     = (const int*)d_in[4];
    const float* W_init   = (const float*)d_in[5];
    const float* b_init   = (const float*)d_in[6];
    const float* W_self   = (const float*)d_in[7];
    const float* b_self   = (const float*)d_in[8];
    const float* W_neigh  = (const float*)d_in[9];
    const float* b_neigh  = (const float*)d_in[10];
    float*       out      = (float*)d_out;

    float *h0, *h1, *agg0, *agg1;
    int *off0, *esrc0, *off1, *esrc1;
    cudaGetSymbolAddress((void**)&h0, g_h0);
    cudaGetSymbolAddress((void**)&h1, g_h1);
    cudaGetSymbolAddress((void**)&agg0, g_agg0);
    cudaGetSymbolAddress((void**)&agg1, g_agg1);
    cudaGetSymbolAddress((void**)&off0, g_off0);
    cudaGetSymbolAddress((void**)&esrc0, g_esrc0);
    cudaGetSymbolAddress((void**)&off1, g_off1);
    cudaGetSymbolAddress((void**)&esrc1, g_esrc1);

    const int SMEM_BYTES = 3 * 128 * AS * 4;  // 202752
    static bool s_init = false;
    static cudaStream_t s_side;
    static cudaEvent_t ev_fork, ev_csr, ev_h0, ev_self2, ev_h1, ev_self3;
    if (!s_init) {
        cudaFuncSetAttribute(tc_gemm_kernel<1, 0>, cudaFuncAttributeMaxDynamicSharedMemorySize, SMEM_BYTES);
        cudaFuncSetAttribute(tc_gemm_kernel<0, 0>, cudaFuncAttributeMaxDynamicSharedMemorySize, SMEM_BYTES);
        cudaFuncSetAttribute(tc_gemm_kernel<1, 1>, cudaFuncAttributeMaxDynamicSharedMemorySize, SMEM_BYTES);
        cudaFuncSetAttribute(tc_gemm_kernel<0, 1>, cudaFuncAttributeMaxDynamicSharedMemorySize, SMEM_BYTES);
        cudaStreamCreateWithFlags(&s_side, cudaStreamNonBlocking);
        cudaEventCreateWithFlags(&ev_fork, cudaEventDisableTiming);
        cudaEventCreateWithFlags(&ev_csr, cudaEventDisableTiming);
        cudaEventCreateWithFlags(&ev_h0, cudaEventDisableTiming);
        cudaEventCreateWithFlags(&ev_self2, cudaEventDisableTiming);
        cudaEventCreateWithFlags(&ev_h1, cudaEventDisableTiming);
        cudaEventCreateWithFlags(&ev_self3, cudaEventDisableTiming);
        s_init = true;
    }

    // ---- fork: CSR chain on side stream, GEMM1 on main stream ----
    cudaEventRecord(ev_fork, 0);
    cudaStreamWaitEvent(s_side, ev_fork, 0);

    zero_counts_kernel<<<(NDST0 + 255) / 256, 256, 0, s_side>>>();
    hist_kernel<<<(E0 + 255) / 256, 256, 0, s_side>>>(dst0, dst1);
    scan_blocks_kernel<<<NB0 + NB1, 1024, 0, s_side>>>();
    scan_tops_kernel<<<1, 64, 0, s_side>>>();
    scan_apply_kernel<<<NB0 + NB1, 1024, 0, s_side>>>();
    scatter_kernel<<<(E0 + 255) / 256, 256, 0, s_side>>>(src0, dst0, src1, dst1);
    cudaEventRecord(ev_csr, s_side);

    // --- layer 0 (main): h0 = relu(features @ W_init + b_init) ---
    tc_gemm_kernel<1, 0><<<148, 256, SMEM_BYTES>>>(features, W_init, b_init, h0, NSRC0);
    cudaEventRecord(ev_h0, 0);

    // --- side: selfGEMM2 (pre-activation partial) concurrent with agg0 ---
    cudaStreamWaitEvent(s_side, ev_h0, 0);
    tc_gemm_kernel<0, 0><<<148, 256, SMEM_BYTES, s_side>>>(h0, W_self, b_self, h1, NDST0);
    cudaEventRecord(ev_self2, s_side);

    // --- main: agg0 (needs h0 + CSR) ---
    cudaStreamWaitEvent(0, ev_csr, 0);
    aggregate_kernel<<<(NDST0 * 32 + 255) / 256, 256>>>(h0, off0, esrc0, agg0, NDST0);

    // --- main: neighGEMM2 accumulates + relu -> h1 ---
    cudaStreamWaitEvent(0, ev_self2, 0);
    tc_gemm_kernel<1, 1><<<148, 256, SMEM_BYTES>>>(agg0, W_neigh, b_neigh, h1, NDST0);
    cudaEventRecord(ev_h1, 0);

    // --- side: selfGEMM3 (pre-activation partial) concurrent with agg1 ---
    cudaStreamWaitEvent(s_side, ev_h1, 0);
    tc_gemm_kernel<0, 0><<<79, 256, SMEM_BYTES, s_side>>>(h1, W_self, b_self, out, NDST1);
    cudaEventRecord(ev_self3, s_side);

    // --- main: agg1 ---
    aggregate_kernel<<<(NDST1 * 32 + 255) / 256, 256>>>(h1, off1, esrc1, agg1, NDST1);

    // --- main: neighGEMM3 accumulates (no relu) -> out ---
    cudaStreamWaitEvent(0, ev_self3, 0);
    tc_gemm_kernel<0, 1><<<79, 256, SMEM_BYTES>>>(agg1, W_neigh, b_neigh, out, NDST1);
}